// round 2
// baseline (speedup 1.0000x reference)
#include <cuda_runtime.h>

// ---------------- problem constants ----------------
#define B_    8
#define HDIM  112
#define WDIM  112
#define CDIM  384
#define NHEAD 12
#define HD    32
#define WS    7
#define SSH   3
#define NTOK  49          // WS*WS
#define NWH   16          // HDIM/WS
#define NWW   16
#define NWIN  256         // NWH*NWW
#define BW    (B_ * NWIN)         // 2048 windows total
#define MROWS (BW * NTOK)         // 100352
#define QKVN  (3 * CDIM)          // 1152

// GEMM tiling
#define BM 128
#define BN 64
#define BK 16

// ---------------- scratch (static device globals; no allocation) ----------------
__device__ float gQ[(size_t)BW * NHEAD * NTOK * HD];   // 154 MB
__device__ float gK[(size_t)BW * NHEAD * NTOK * HD];   // 154 MB
__device__ float gV[(size_t)BW * NHEAD * NTOK * HD];   // 154 MB
__device__ float gAttnOut[(size_t)MROWS * CDIM];       // 154 MB
__device__ float gBias[NHEAD * NTOK * NTOK];           // 115 KB

// ---------------- shift/window <-> original row mapping (bijection, no padding) -
__device__ __forceinline__ int src_row(int m) {
    int w  = m / NTOK;
    int n  = m - w * NTOK;
    int b  = w / NWIN;
    int wi = w - b * NWIN;
    int wy = wi / NWW;
    int wx = wi - wy * NWW;
    int ty = n / WS;
    int tx = n - ty * WS;
    int sy = wy * WS + ty;
    int sx = wx * WS + tx;
    int oy = sy + SSH; if (oy >= HDIM) oy -= HDIM;   // shifted[s] = orig[(s+SS)%H]
    int ox = sx + SSH; if (ox >= WDIM) ox -= WDIM;
    return (b * HDIM + oy) * WDIM + ox;              // row in (B*H*W)
}

// ---------------- relative position bias table expansion ----------------
__global__ void bias_kernel(const float* __restrict__ rel_pos_table) {
    int idx = blockIdx.x * blockDim.x + threadIdx.x;
    if (idx >= NHEAD * NTOK * NTOK) return;
    int h = idx / (NTOK * NTOK);
    int r = idx - h * (NTOK * NTOK);
    int i = r / NTOK;
    int j = r - i * NTOK;
    // c(n) = (2*WS-1)*(n/WS) + n%WS ; ridx[i][j] = c(i) + c(WS*WS-1-j)
    int ci = 13 * (i / 7) + (i % 7);
    int jr = 48 - j;
    int cj = 13 * (jr / 7) + (jr % 7);
    gBias[idx] = rel_pos_table[(ci + cj) * NHEAD + h];
}

// ---------------- K1: QKV GEMM fused with shifted-window gather ----------------
// C[m, col] = sum_k x[src_row(m), k] * qkv_w[k, col] + qkv_b[col]
// scatter: col -> (t, h, d); write Q/K/V[w][h][n][d]
__global__ __launch_bounds__(256) void qkv_gemm(const float* __restrict__ x,
                                                const float* __restrict__ qkv_w,
                                                const float* __restrict__ qkv_b) {
    __shared__ float As[BK][BM];
    __shared__ float Bs[BK][BN];
    __shared__ int   rowIdx[BM];

    int tid = threadIdx.x;
    int m0  = blockIdx.x * BM;
    int bn  = blockIdx.y;

    if (tid < BM) rowIdx[tid] = src_row(m0 + tid);
    __syncthreads();

    float acc[8][4] = {};
    int ty = tid >> 4;        // 0..15 -> 8 rows each
    int tx = tid & 15;        // 0..15 -> 4 cols each
    int qd = tid & 3;         // A-load: quad within row
    int r0 = tid >> 2;        // A-load: row 0..63 (+64)
    int br = tid >> 4;        // B-load: k row 0..15
    int bc = (tid & 15) * 4;  // B-load: col

    for (int kt = 0; kt < CDIM / BK; ++kt) {
        int k0 = kt * BK;
#pragma unroll
        for (int s = 0; s < 2; ++s) {
            int r = r0 + s * 64;
            float4 a = *(const float4*)(x + (size_t)rowIdx[r] * CDIM + k0 + qd * 4);
            As[qd * 4 + 0][r] = a.x;
            As[qd * 4 + 1][r] = a.y;
            As[qd * 4 + 2][r] = a.z;
            As[qd * 4 + 3][r] = a.w;
        }
        *(float4*)&Bs[br][bc] =
            *(const float4*)(qkv_w + (size_t)(k0 + br) * QKVN + bn * BN + bc);
        __syncthreads();
#pragma unroll
        for (int k = 0; k < BK; ++k) {
            float4 a0 = *(float4*)&As[k][ty * 8];
            float4 a1 = *(float4*)&As[k][ty * 8 + 4];
            float4 b  = *(float4*)&Bs[k][tx * 4];
            float av[8] = {a0.x, a0.y, a0.z, a0.w, a1.x, a1.y, a1.z, a1.w};
            float bv[4] = {b.x, b.y, b.z, b.w};
#pragma unroll
            for (int i = 0; i < 8; ++i)
#pragma unroll
                for (int j = 0; j < 4; ++j) acc[i][j] += av[i] * bv[j];
        }
        __syncthreads();
    }

    int col = bn * BN + tx * 4;          // multiple of 4; 64-wide block within one t
    int t   = col / CDIM;                // 0=Q 1=K 2=V
    int cc  = col - t * CDIM;
    int h   = cc / HD;                   // 4-col group never straddles a head
    int d   = cc - h * HD;
    float* dstT = (t == 0) ? gQ : (t == 1) ? gK : gV;
    float4 bb = *(const float4*)(qkv_b + col);
#pragma unroll
    for (int i = 0; i < 8; ++i) {
        int m = m0 + ty * 8 + i;
        int w = m / NTOK;
        int n = m - w * NTOK;
        float4 v = make_float4(acc[i][0] + bb.x, acc[i][1] + bb.y,
                               acc[i][2] + bb.z, acc[i][3] + bb.w);
        *(float4*)(dstT + ((size_t)(w * NHEAD + h) * NTOK + n) * HD + d) = v;
    }
}

// ---------------- K2: per-(window,head) attention ----------------
__global__ __launch_bounds__(64) void attn_kernel() {
    const float scale = 0.17677669529663689f;  // 32^-0.5
    int bid = blockIdx.x;
    int w   = bid / NHEAD;
    int h   = bid - w * NHEAD;

    __shared__ float Qs[NTOK][HD];
    __shared__ float Ks[NTOK][HD];
    __shared__ float Vs[NTOK][HD];
    __shared__ float Ps[NTOK][NTOK];   // softmax probabilities (stride 49: odd -> conflict-free)
    __shared__ int   rcnt[NTOK];

    int tid = threadIdx.x;
    size_t base = (size_t)(w * NHEAD + h) * NTOK * HD;

    for (int idx = tid; idx < NTOK * HD; idx += 64) {
        ((float*)Qs)[idx] = gQ[base + idx] * scale;
        ((float*)Ks)[idx] = gK[base + idx];
        ((float*)Vs)[idx] = gV[base + idx];
    }
    if (tid < NTOK) {
        int wi = w % NWIN;
        int wy = wi / NWW, wx = wi - wy * NWW;
        int ty = tid / WS, tx = tid - ty * WS;
        int sy = wy * WS + ty, sx = wx * WS + tx;
        int idh = (sy < HDIM - WS) ? 0 : (sy < HDIM - SSH) ? 1 : 2;
        int idw = (sx < WDIM - WS) ? 0 : (sx < WDIM - SSH) ? 1 : 2;
        rcnt[tid] = idh * 3 + idw;
    }
    __syncthreads();

    if (tid < NTOK) {
        float q[HD];
#pragma unroll
        for (int d = 0; d < HD; ++d) q[d] = Qs[tid][d];

        const float* biasRow = gBias + (h * NTOK + tid) * NTOK;
        int myc = rcnt[tid];
        float mx = -1e30f;
        for (int j = 0; j < NTOK; ++j) {
            float s = 0.f;
#pragma unroll
            for (int d = 0; d < HD; d += 4) {
                float4 kv = *(float4*)&Ks[j][d];
                s += q[d] * kv.x + q[d + 1] * kv.y + q[d + 2] * kv.z + q[d + 3] * kv.w;
            }
            s += biasRow[j];
            if (rcnt[j] != myc) s -= 100.0f;
            Ps[tid][j] = s;
            mx = fmaxf(mx, s);
        }
        float sum = 0.f;
        for (int j = 0; j < NTOK; ++j) {
            float e = __expf(Ps[tid][j] - mx);
            Ps[tid][j] = e;
            sum += e;
        }
        float inv = 1.0f / sum;

        float o[HD] = {};
        for (int j = 0; j < NTOK; ++j) {
            float pj = Ps[tid][j] * inv;
#pragma unroll
            for (int d = 0; d < HD; d += 4) {
                float4 vv = *(float4*)&Vs[j][d];
                o[d]     += pj * vv.x;
                o[d + 1] += pj * vv.y;
                o[d + 2] += pj * vv.z;
                o[d + 3] += pj * vv.w;
            }
        }
        float* dst = gAttnOut + (size_t)(w * NTOK + tid) * CDIM + h * HD;
#pragma unroll
        for (int d = 0; d < HD; d += 4)
            *(float4*)(dst + d) = make_float4(o[d], o[d + 1], o[d + 2], o[d + 3]);
    }
}

// ---------------- K3: proj GEMM fused with window-reverse + roll scatter --------
__global__ __launch_bounds__(256) void proj_gemm(const float* __restrict__ pw,
                                                 const float* __restrict__ pb,
                                                 float* __restrict__ out) {
    __shared__ float As[BK][BM];
    __shared__ float Bs[BK][BN];

    int tid = threadIdx.x;
    int m0  = blockIdx.x * BM;
    int bn  = blockIdx.y;

    float acc[8][4] = {};
    int ty = tid >> 4;
    int tx = tid & 15;
    int qd = tid & 3;
    int r0 = tid >> 2;
    int br = tid >> 4;
    int bc = (tid & 15) * 4;

    for (int kt = 0; kt < CDIM / BK; ++kt) {
        int k0 = kt * BK;
#pragma unroll
        for (int s = 0; s < 2; ++s) {
            int r = r0 + s * 64;
            float4 a = *(const float4*)(gAttnOut + (size_t)(m0 + r) * CDIM + k0 + qd * 4);
            As[qd * 4 + 0][r] = a.x;
            As[qd * 4 + 1][r] = a.y;
            As[qd * 4 + 2][r] = a.z;
            As[qd * 4 + 3][r] = a.w;
        }
        *(float4*)&Bs[br][bc] =
            *(const float4*)(pw + (size_t)(k0 + br) * CDIM + bn * BN + bc);
        __syncthreads();
#pragma unroll
        for (int k = 0; k < BK; ++k) {
            float4 a0 = *(float4*)&As[k][ty * 8];
            float4 a1 = *(float4*)&As[k][ty * 8 + 4];
            float4 b  = *(float4*)&Bs[k][tx * 4];
            float av[8] = {a0.x, a0.y, a0.z, a0.w, a1.x, a1.y, a1.z, a1.w};
            float bv[4] = {b.x, b.y, b.z, b.w};
#pragma unroll
            for (int i = 0; i < 8; ++i)
#pragma unroll
                for (int j = 0; j < 4; ++j) acc[i][j] += av[i] * bv[j];
        }
        __syncthreads();
    }

    int col = bn * BN + tx * 4;
    float4 bb = *(const float4*)(pb + col);
#pragma unroll
    for (int i = 0; i < 8; ++i) {
        int m = m0 + ty * 8 + i;
        int orow = src_row(m);   // inverse shift == forward mapping (bijection)
        float4 v = make_float4(acc[i][0] + bb.x, acc[i][1] + bb.y,
                               acc[i][2] + bb.z, acc[i][3] + bb.w);
        *(float4*)(out + (size_t)orow * CDIM + col) = v;
    }
}

// ---------------- launch ----------------
extern "C" void kernel_launch(void* const* d_in, const int* in_sizes, int n_in,
                              void* d_out, int out_size) {
    (void)in_sizes; (void)n_in; (void)out_size;
    const float* x      = (const float*)d_in[0];
    const float* qkv_w  = (const float*)d_in[1];
    const float* qkv_b  = (const float*)d_in[2];
    const float* proj_w = (const float*)d_in[3];
    const float* proj_b = (const float*)d_in[4];
    const float* rpt    = (const float*)d_in[5];
    float* out = (float*)d_out;

    bias_kernel<<<(NHEAD * NTOK * NTOK + 255) / 256, 256>>>(rpt);

    dim3 g1(MROWS / BM, QKVN / BN);   // (784, 18)
    qkv_gemm<<<g1, 256>>>(x, qkv_w, qkv_b);

    attn_kernel<<<BW * NHEAD, 64>>>();  // 24576 blocks

    dim3 g3(MROWS / BM, CDIM / BN);   // (784, 6)
    proj_gemm<<<g3, 256>>>(proj_w, proj_b, out);
}

// round 4
// speedup vs baseline: 1.3159x; 1.3159x over previous
#include <cuda_runtime.h>
#include <cuda_bf16.h>
#include <cstdint>

// ---------------- problem constants ----------------
#define B_    8
#define HDIM  112
#define WDIM  112
#define CDIM  384
#define NHEAD 12
#define HD    32
#define WS    7
#define SSH   3
#define NTOK  49
#define NWH   16
#define NWW   16
#define NWIN  256
#define BW    (B_ * NWIN)          // 2048 windows
#define MROWS (BW * NTOK)          // 100352
#define QKVN  (3 * CDIM)           // 1152

// GEMM tiling (HMMA mma.sync)
#define TM   128
#define TN   128
#define KC   64                    // bf16 per K-chunk
#define NCH  (CDIM / KC)           // 6
#define ROWB 144                   // smem row stride bytes (64*2 + 16 pad) -> conflict-free
#define TILEB (128 * ROWB)         // 18432 per tile
#define STAGEB (4 * TILEB)         // Ahi,Alo,Bhi,Blo = 73728
#define SMEM_SZ (2 * STAGEB)       // 147456

// ---------------- scratch (static device globals) ----------------
__device__ float gQ[(size_t)BW * NHEAD * NTOK * HD];
__device__ float gK[(size_t)BW * NHEAD * NTOK * HD];
__device__ float gV[(size_t)BW * NHEAD * NTOK * HD];
__device__ __nv_bfloat16 gXhi[(size_t)MROWS * CDIM];
__device__ __nv_bfloat16 gXlo[(size_t)MROWS * CDIM];
__device__ __nv_bfloat16 gOhi[(size_t)MROWS * CDIM];
__device__ __nv_bfloat16 gOlo[(size_t)MROWS * CDIM];
__device__ __nv_bfloat16 gWhi[(size_t)QKVN * CDIM];
__device__ __nv_bfloat16 gWlo[(size_t)QKVN * CDIM];
__device__ __nv_bfloat16 gPhi[(size_t)CDIM * CDIM];
__device__ __nv_bfloat16 gPlo[(size_t)CDIM * CDIM];
__device__ float gBias[NHEAD * NTOK * NTOK];

// ---------------- helpers ----------------
#define CP_ASYNC16(dst, src) \
    asm volatile("cp.async.cg.shared.global [%0], [%1], 16;" :: "r"(dst), "l"(src))
#define CP_COMMIT() asm volatile("cp.async.commit_group;" ::: "memory")
#define CP_WAIT(n)  asm volatile("cp.async.wait_group %0;" :: "n"(n) : "memory")

__device__ __forceinline__ uint32_t smem_u32(const void* p) {
    uint32_t a;
    asm("{ .reg .u64 t; cvta.to.shared.u64 t, %1; cvt.u32.u64 %0, t; }" : "=r"(a) : "l"(p));
    return a;
}

__device__ __forceinline__ void mma16816(float* c, const uint32_t* a, const uint32_t* b) {
    asm volatile(
        "mma.sync.aligned.m16n8k16.row.col.f32.bf16.bf16.f32 "
        "{%0,%1,%2,%3}, {%4,%5,%6,%7}, {%8,%9}, {%0,%1,%2,%3};"
        : "+f"(c[0]), "+f"(c[1]), "+f"(c[2]), "+f"(c[3])
        : "r"(a[0]), "r"(a[1]), "r"(a[2]), "r"(a[3]), "r"(b[0]), "r"(b[1]));
}

// ---------------- shift/window row mapping (bijection, no padding) ---------------
__device__ __forceinline__ int src_row(int m) {
    int w  = m / NTOK;
    int n  = m - w * NTOK;
    int b  = w / NWIN;
    int wi = w - b * NWIN;
    int wy = wi / NWW;
    int wx = wi - wy * NWW;
    int ty = n / WS;
    int tx = n - ty * WS;
    int sy = wy * WS + ty;
    int sx = wx * WS + tx;
    int oy = sy + SSH; if (oy >= HDIM) oy -= HDIM;
    int ox = sx + SSH; if (ox >= WDIM) ox -= WDIM;
    return (b * HDIM + oy) * WDIM + ox;
}

__device__ __forceinline__ void split2(float a, float b, uint32_t& hi, uint32_t& lo) {
    __nv_bfloat16 ha = __float2bfloat16_rn(a);
    __nv_bfloat16 hb = __float2bfloat16_rn(b);
    __nv_bfloat16 la = __float2bfloat16_rn(a - __bfloat162float(ha));
    __nv_bfloat16 lb = __float2bfloat16_rn(b - __bfloat162float(hb));
    __nv_bfloat162 h2 = __nv_bfloat162(ha, hb);
    __nv_bfloat162 l2 = __nv_bfloat162(la, lb);
    hi = *reinterpret_cast<uint32_t*>(&h2);
    lo = *reinterpret_cast<uint32_t*>(&l2);
}

// ---------------- prep kernels ----------------
__global__ void bias_kernel(const float* __restrict__ rel_pos_table) {
    int idx = blockIdx.x * blockDim.x + threadIdx.x;
    if (idx >= NHEAD * NTOK * NTOK) return;
    int h = idx / (NTOK * NTOK);
    int r = idx - h * (NTOK * NTOK);
    int i = r / NTOK;
    int j = r - i * NTOK;
    int ci = 13 * (i / 7) + (i % 7);
    int jr = 48 - j;
    int cj = 13 * (jr / 7) + (jr % 7);
    gBias[idx] = rel_pos_table[(ci + cj) * NHEAD + h];
}

__global__ __launch_bounds__(256) void split_gather(const float* __restrict__ x) {
    int t = blockIdx.x * blockDim.x + threadIdx.x;
    if (t >= MROWS * (CDIM / 4)) return;
    int m = t / (CDIM / 4);
    int q = t - m * (CDIM / 4);
    float4 v = *(const float4*)(x + (size_t)src_row(m) * CDIM + q * 4);
    uint32_t h0, l0, h1, l1;
    split2(v.x, v.y, h0, l0);
    split2(v.z, v.w, h1, l1);
    size_t o = (size_t)m * CDIM + q * 4;
    *(uint2*)(gXhi + o) = make_uint2(h0, h1);
    *(uint2*)(gXlo + o) = make_uint2(l0, l1);
}

__global__ void wsplit(const float* __restrict__ src, __nv_bfloat16* dhi,
                       __nv_bfloat16* dlo, int N, int K) {
    int t = blockIdx.x * blockDim.x + threadIdx.x;
    if (t >= N * K) return;
    int n = t / K;
    int k = t - n * K;
    float v = src[(size_t)k * N + n];
    __nv_bfloat16 h = __float2bfloat16_rn(v);
    __nv_bfloat16 l = __float2bfloat16_rn(v - __bfloat162float(h));
    dhi[t] = h;
    dlo[t] = l;
}

// ---------------- HMMA GEMM: C[m,n] = sum_k A[m,k]*B[n,k] + bias[n] --------------
__device__ __forceinline__ void load_stage(uint32_t sbuf, int tid,
        const __nv_bfloat16* Ahi, const __nv_bfloat16* Alo,
        const __nv_bfloat16* Bhi, const __nv_bfloat16* Blo,
        int m0, int n0, int k0) {
#pragma unroll
    for (int i = 0; i < 16; ++i) {
        int q    = tid + i * 256;
        int tile = q >> 10;          // 0..3
        int idx  = q & 1023;
        int r    = idx >> 3;         // row 0..127
        int c    = idx & 7;          // 16B chunk 0..7
        const __nv_bfloat16* srcp;
        if (tile == 0)      srcp = Ahi + (size_t)(m0 + r) * CDIM + k0 + c * 8;
        else if (tile == 1) srcp = Alo + (size_t)(m0 + r) * CDIM + k0 + c * 8;
        else if (tile == 2) srcp = Bhi + (size_t)(n0 + r) * CDIM + k0 + c * 8;
        else                srcp = Blo + (size_t)(n0 + r) * CDIM + k0 + c * 8;
        uint32_t dst = sbuf + tile * TILEB + r * ROWB + c * 16;
        CP_ASYNC16(dst, srcp);
    }
}

__global__ __launch_bounds__(256) void mma_gemm(
        const __nv_bfloat16* __restrict__ Ahi, const __nv_bfloat16* __restrict__ Alo,
        const __nv_bfloat16* __restrict__ Bhi, const __nv_bfloat16* __restrict__ Blo,
        const float* __restrict__ bias, float* __restrict__ outp, int mode) {
    extern __shared__ char smem[];
    uint32_t sb = smem_u32(smem);

    int tid  = threadIdx.x;
    int wid  = tid >> 5;
    int lane = tid & 31;
    int wm   = wid & 3;          // 4 warps over M (32 rows each)
    int wn   = wid >> 2;         // 2 warps over N (64 cols each)
    int n0   = blockIdx.x * TN;
    int m0   = blockIdx.y * TM;

    float acc[2][8][4];
#pragma unroll
    for (int i = 0; i < 2; ++i)
#pragma unroll
        for (int j = 0; j < 8; ++j)
#pragma unroll
            for (int k = 0; k < 4; ++k) acc[i][j][k] = 0.f;

    load_stage(sb, tid, Ahi, Alo, Bhi, Blo, m0, n0, 0);
    CP_COMMIT();
    load_stage(sb + STAGEB, tid, Ahi, Alo, Bhi, Blo, m0, n0, KC);
    CP_COMMIT();

    int g  = (lane >> 2);        // 0..7
    int cq = (lane & 3);         // 0..3

#pragma unroll 1
    for (int s = 0; s < NCH; ++s) {
        if (s < NCH - 1) { CP_WAIT(1); } else { CP_WAIT(0); }
        __syncthreads();
        const char* st = smem + (s & 1) * STAGEB;
        const char* pAh = st;
        const char* pAl = st + TILEB;
        const char* pBh = st + 2 * TILEB;
        const char* pBl = st + 3 * TILEB;

#pragma unroll
        for (int ks = 0; ks < 4; ++ks) {
            int kb = ks * 32 + cq * 4;          // byte offset of this lane's k-pair
            uint32_t ah[2][4], al[2][4];
#pragma unroll
            for (int mf = 0; mf < 2; ++mf) {
                int r = wm * 32 + mf * 16 + g;
                ah[mf][0] = *(const uint32_t*)(pAh + r * ROWB + kb);
                ah[mf][1] = *(const uint32_t*)(pAh + (r + 8) * ROWB + kb);
                ah[mf][2] = *(const uint32_t*)(pAh + r * ROWB + kb + 16);
                ah[mf][3] = *(const uint32_t*)(pAh + (r + 8) * ROWB + kb + 16);
                al[mf][0] = *(const uint32_t*)(pAl + r * ROWB + kb);
                al[mf][1] = *(const uint32_t*)(pAl + (r + 8) * ROWB + kb);
                al[mf][2] = *(const uint32_t*)(pAl + r * ROWB + kb + 16);
                al[mf][3] = *(const uint32_t*)(pAl + (r + 8) * ROWB + kb + 16);
            }
            uint32_t bh[8][2], bl[8][2];
#pragma unroll
            for (int nf = 0; nf < 8; ++nf) {
                int r = wn * 64 + nf * 8 + g;
                bh[nf][0] = *(const uint32_t*)(pBh + r * ROWB + kb);
                bh[nf][1] = *(const uint32_t*)(pBh + r * ROWB + kb + 16);
                bl[nf][0] = *(const uint32_t*)(pBl + r * ROWB + kb);
                bl[nf][1] = *(const uint32_t*)(pBl + r * ROWB + kb + 16);
            }
#pragma unroll
            for (int mf = 0; mf < 2; ++mf)
#pragma unroll
                for (int nf = 0; nf < 8; ++nf) {
                    mma16816(acc[mf][nf], ah[mf], bh[nf]);
                    mma16816(acc[mf][nf], ah[mf], bl[nf]);
                    mma16816(acc[mf][nf], al[mf], bh[nf]);
                }
        }
        __syncthreads();
        if (s + 2 < NCH) {
            load_stage(sb + (s & 1) * STAGEB, tid, Ahi, Alo, Bhi, Blo, m0, n0, (s + 2) * KC);
            CP_COMMIT();
        }
    }

    // ---- epilogue ----
#pragma unroll
    for (int mf = 0; mf < 2; ++mf) {
#pragma unroll
        for (int nf = 0; nf < 8; ++nf) {
            int cn   = n0 + wn * 64 + nf * 8 + cq * 2;
            int row0 = m0 + wm * 32 + mf * 16 + g;
            float2 bb = *(const float2*)(bias + cn);
            float v00 = acc[mf][nf][0] + bb.x, v01 = acc[mf][nf][1] + bb.y;
            float v10 = acc[mf][nf][2] + bb.x, v11 = acc[mf][nf][3] + bb.y;
            if (mode == 0) {
                int t   = cn / CDIM;
                int rem = cn - t * CDIM;
                int hh  = rem >> 5;
                int d   = rem & 31;
                float* basep = (t == 0) ? gQ : (t == 1) ? gK : gV;
#pragma unroll
                for (int rr = 0; rr < 2; ++rr) {
                    int m  = row0 + rr * 8;
                    int w  = m / NTOK;
                    int nn = m - w * NTOK;
                    float* dst = basep + ((size_t)(w * NHEAD + hh) * NTOK + nn) * HD + d;
                    *(float2*)dst = (rr == 0) ? make_float2(v00, v01) : make_float2(v10, v11);
                }
            } else {
#pragma unroll
                for (int rr = 0; rr < 2; ++rr) {
                    int m = row0 + rr * 8;
                    int orow = src_row(m);
                    *(float2*)(outp + (size_t)orow * CDIM + cn) =
                        (rr == 0) ? make_float2(v00, v01) : make_float2(v10, v11);
                }
            }
        }
    }
}

// ---------------- attention (SIMT; emits hi/lo bf16 for GEMM2) -------------------
__global__ __launch_bounds__(64) void attn_kernel() {
    const float scale = 0.17677669529663689f;
    int bid = blockIdx.x;
    int w   = bid / NHEAD;
    int h   = bid - w * NHEAD;

    __shared__ float Qs[NTOK][HD];
    __shared__ float Ks[NTOK][HD];
    __shared__ float Vs[NTOK][HD];
    __shared__ float Ps[NTOK][NTOK];
    __shared__ int   rcnt[NTOK];

    int tid = threadIdx.x;
    size_t base = (size_t)(w * NHEAD + h) * NTOK * HD;

    for (int idx = tid; idx < NTOK * HD; idx += 64) {
        ((float*)Qs)[idx] = gQ[base + idx] * scale;
        ((float*)Ks)[idx] = gK[base + idx];
        ((float*)Vs)[idx] = gV[base + idx];
    }
    if (tid < NTOK) {
        int wi = w % NWIN;
        int wy = wi / NWW, wx = wi - wy * NWW;
        int ty = tid / WS, tx = tid - ty * WS;
        int sy = wy * WS + ty, sx = wx * WS + tx;
        int idh = (sy < HDIM - WS) ? 0 : (sy < HDIM - SSH) ? 1 : 2;
        int idw = (sx < WDIM - WS) ? 0 : (sx < WDIM - SSH) ? 1 : 2;
        rcnt[tid] = idh * 3 + idw;
    }
    __syncthreads();

    if (tid < NTOK) {
        float q[HD];
#pragma unroll
        for (int d = 0; d < HD; ++d) q[d] = Qs[tid][d];

        const float* biasRow = gBias + (h * NTOK + tid) * NTOK;
        int myc = rcnt[tid];
        float mx = -1e30f;
        for (int j = 0; j < NTOK; ++j) {
            float s = 0.f;
#pragma unroll
            for (int d = 0; d < HD; d += 4) {
                float4 kv = *(float4*)&Ks[j][d];
                s += q[d] * kv.x + q[d + 1] * kv.y + q[d + 2] * kv.z + q[d + 3] * kv.w;
            }
            s += biasRow[j];
            if (rcnt[j] != myc) s -= 100.0f;
            Ps[tid][j] = s;
            mx = fmaxf(mx, s);
        }
        float sum = 0.f;
        for (int j = 0; j < NTOK; ++j) {
            float e = __expf(Ps[tid][j] - mx);
            Ps[tid][j] = e;
            sum += e;
        }
        float inv = 1.0f / sum;

        float o[HD] = {};
        for (int j = 0; j < NTOK; ++j) {
            float pj = Ps[tid][j] * inv;
#pragma unroll
            for (int d = 0; d < HD; d += 4) {
                float4 vv = *(float4*)&Vs[j][d];
                o[d]     += pj * vv.x;
                o[d + 1] += pj * vv.y;
                o[d + 2] += pj * vv.z;
                o[d + 3] += pj * vv.w;
            }
        }
        size_t dstoff = (size_t)(w * NTOK + tid) * CDIM + h * HD;
#pragma unroll
        for (int d = 0; d < HD; d += 4) {
            uint32_t h0, l0, h1, l1;
            split2(o[d], o[d + 1], h0, l0);
            split2(o[d + 2], o[d + 3], h1, l1);
            *(uint2*)(gOhi + dstoff + d) = make_uint2(h0, h1);
            *(uint2*)(gOlo + dstoff + d) = make_uint2(l0, l1);
        }
    }
}

// ---------------- launch ----------------
extern "C" void kernel_launch(void* const* d_in, const int* in_sizes, int n_in,
                              void* d_out, int out_size) {
    (void)in_sizes; (void)n_in; (void)out_size;
    const float* x      = (const float*)d_in[0];
    const float* qkv_w  = (const float*)d_in[1];
    const float* qkv_b  = (const float*)d_in[2];
    const float* proj_w = (const float*)d_in[3];
    const float* proj_b = (const float*)d_in[4];
    const float* rpt    = (const float*)d_in[5];
    float* out = (float*)d_out;

    cudaFuncSetAttribute(mma_gemm, cudaFuncAttributeMaxDynamicSharedMemorySize, SMEM_SZ);

    __nv_bfloat16 *pXhi, *pXlo, *pOhi, *pOlo, *pWhi, *pWlo, *pPhi, *pPlo;
    cudaGetSymbolAddress((void**)&pXhi, gXhi);
    cudaGetSymbolAddress((void**)&pXlo, gXlo);
    cudaGetSymbolAddress((void**)&pOhi, gOhi);
    cudaGetSymbolAddress((void**)&pOlo, gOlo);
    cudaGetSymbolAddress((void**)&pWhi, gWhi);
    cudaGetSymbolAddress((void**)&pWlo, gWlo);
    cudaGetSymbolAddress((void**)&pPhi, gPhi);
    cudaGetSymbolAddress((void**)&pPlo, gPlo);

    bias_kernel<<<(NHEAD * NTOK * NTOK + 255) / 256, 256>>>(rpt);
    split_gather<<<(MROWS * (CDIM / 4) + 255) / 256, 256>>>(x);
    wsplit<<<(QKVN * CDIM + 255) / 256, 256>>>(qkv_w, pWhi, pWlo, QKVN, CDIM);
    wsplit<<<(CDIM * CDIM + 255) / 256, 256>>>(proj_w, pPhi, pPlo, CDIM, CDIM);

    dim3 g1(QKVN / TN, MROWS / TM);   // (9, 784)
    mma_gemm<<<g1, 256, SMEM_SZ>>>(pXhi, pXlo, pWhi, pWlo, qkv_b, nullptr, 0);

    attn_kernel<<<BW * NHEAD, 64>>>();

    dim3 g2(CDIM / TN, MROWS / TM);   // (3, 784)
    mma_gemm<<<g2, 256, SMEM_SZ>>>(pOhi, pOlo, pPhi, pPlo, proj_b, out, 1);
}

// round 5
// speedup vs baseline: 3.5904x; 2.7285x over previous
#include <cuda_runtime.h>
#include <cuda_fp16.h>
#include <cstdint>

// ---------------- problem constants ----------------
#define B_    8
#define HDIM  112
#define WDIM  112
#define CDIM  384
#define NHEAD 12
#define HD    32
#define WS    7
#define SSH   3
#define NTOK  49
#define NWH   16
#define NWW   16
#define NWIN  256
#define BW    (B_ * NWIN)          // 2048 windows
#define MROWS (BW * NTOK)          // 100352
#define QKVN  (3 * CDIM)           // 1152

// GEMM tiling (HMMA mma.sync, fp16 single pass)
#define TM   128
#define TN   128
#define KC   64                    // fp16 elements per K-chunk
#define NCH  (CDIM / KC)           // 6
#define ROWB 144                   // smem row stride bytes (64*2 + 16 pad)
#define TILEB (128 * ROWB)         // 18432
#define STAGEB (2 * TILEB)         // A,B = 36864
#define SMEM_SZ (2 * STAGEB)       // 73728

// ---------------- scratch ----------------
__device__ float gQ[(size_t)BW * NHEAD * NTOK * HD];
__device__ float gK[(size_t)BW * NHEAD * NTOK * HD];
__device__ float gV[(size_t)BW * NHEAD * NTOK * HD];
__device__ __half gXh[(size_t)MROWS * CDIM];
__device__ __half gOh[(size_t)MROWS * CDIM];
__device__ __half gWh[(size_t)QKVN * CDIM];
__device__ __half gPh[(size_t)CDIM * CDIM];
__device__ float gBias[NHEAD * NTOK * NTOK];

// ---------------- helpers ----------------
#define CP_ASYNC16(dst, src) \
    asm volatile("cp.async.cg.shared.global [%0], [%1], 16;" :: "r"(dst), "l"(src))
#define CP_COMMIT() asm volatile("cp.async.commit_group;" ::: "memory")
#define CP_WAIT(n)  asm volatile("cp.async.wait_group %0;" :: "n"(n) : "memory")

__device__ __forceinline__ uint32_t smem_u32(const void* p) {
    uint32_t a;
    asm("{ .reg .u64 t; cvta.to.shared.u64 t, %1; cvt.u32.u64 %0, t; }" : "=r"(a) : "l"(p));
    return a;
}
__device__ __forceinline__ void ldsm_x4(uint32_t* r, uint32_t addr) {
    asm volatile("ldmatrix.sync.aligned.m8n8.x4.shared.b16 {%0,%1,%2,%3}, [%4];"
                 : "=r"(r[0]), "=r"(r[1]), "=r"(r[2]), "=r"(r[3]) : "r"(addr));
}
__device__ __forceinline__ void mma16816(float* c, const uint32_t* a, const uint32_t* b) {
    asm volatile(
        "mma.sync.aligned.m16n8k16.row.col.f32.f16.f16.f32 "
        "{%0,%1,%2,%3}, {%4,%5,%6,%7}, {%8,%9}, {%0,%1,%2,%3};"
        : "+f"(c[0]), "+f"(c[1]), "+f"(c[2]), "+f"(c[3])
        : "r"(a[0]), "r"(a[1]), "r"(a[2]), "r"(a[3]), "r"(b[0]), "r"(b[1]));
}

// ---------------- shift/window row mapping (bijection, no padding) ---------------
__device__ __forceinline__ int src_row(int m) {
    int w  = m / NTOK;
    int n  = m - w * NTOK;
    int b  = w / NWIN;
    int wi = w - b * NWIN;
    int wy = wi / NWW;
    int wx = wi - wy * NWW;
    int ty = n / WS;
    int tx = n - ty * WS;
    int sy = wy * WS + ty;
    int sx = wx * WS + tx;
    int oy = sy + SSH; if (oy >= HDIM) oy -= HDIM;
    int ox = sx + SSH; if (ox >= WDIM) ox -= WDIM;
    return (b * HDIM + oy) * WDIM + ox;
}

// ---------------- prep kernels ----------------
__global__ void bias_kernel(const float* __restrict__ rel_pos_table) {
    int idx = blockIdx.x * blockDim.x + threadIdx.x;
    if (idx >= NHEAD * NTOK * NTOK) return;
    int h = idx / (NTOK * NTOK);
    int r = idx - h * (NTOK * NTOK);
    int i = r / NTOK;
    int j = r - i * NTOK;
    int ci = 13 * (i / 7) + (i % 7);
    int jr = 48 - j;
    int cj = 13 * (jr / 7) + (jr % 7);
    gBias[idx] = rel_pos_table[(ci + cj) * NHEAD + h];
}

__global__ __launch_bounds__(256) void gather_h(const float* __restrict__ x) {
    int t = blockIdx.x * blockDim.x + threadIdx.x;
    if (t >= MROWS * (CDIM / 4)) return;
    int m = t / (CDIM / 4);
    int q = t - m * (CDIM / 4);
    float4 v = *(const float4*)(x + (size_t)src_row(m) * CDIM + q * 4);
    __half2 h0 = __floats2half2_rn(v.x, v.y);
    __half2 h1 = __floats2half2_rn(v.z, v.w);
    *(uint2*)(gXh + (size_t)m * CDIM + q * 4) =
        make_uint2(*(uint32_t*)&h0, *(uint32_t*)&h1);
}

__global__ void wsplit_h(const float* __restrict__ src, __half* dst, int N, int K) {
    int t = blockIdx.x * blockDim.x + threadIdx.x;
    if (t >= N * K) return;
    int n = t / K;
    int k = t - n * K;
    dst[t] = __float2half_rn(src[(size_t)k * N + n]);
}

// ---------------- HMMA GEMM: C[m,n] = sum_k A[m,k]*B[n,k] + bias[n] --------------
__device__ __forceinline__ void load_stage(uint32_t sbuf, int tid,
        const __half* A, const __half* Bm, int m0, int n0, int k0) {
#pragma unroll
    for (int i = 0; i < 8; ++i) {
        int q    = tid + i * 256;
        int tile = q >> 10;          // 0..1
        int idx  = q & 1023;
        int r    = idx >> 3;         // row 0..127
        int c    = idx & 7;          // 16B chunk 0..7
        const __half* srcp = (tile == 0)
            ? A  + (size_t)(m0 + r) * CDIM + k0 + c * 8
            : Bm + (size_t)(n0 + r) * CDIM + k0 + c * 8;
        uint32_t dst = sbuf + tile * TILEB + r * ROWB + c * 16;
        CP_ASYNC16(dst, srcp);
    }
}

__global__ __launch_bounds__(256, 2) void mma_gemm(
        const __half* __restrict__ A, const __half* __restrict__ Bm,
        const float* __restrict__ bias, float* __restrict__ outp, int mode) {
    extern __shared__ char smem[];
    uint32_t sb = smem_u32(smem);

    int tid  = threadIdx.x;
    int wid  = tid >> 5;
    int lane = tid & 31;
    int wm   = wid & 3;          // 4 warps over M (32 rows)
    int wn   = wid >> 2;         // 2 warps over N (64 cols)
    int n0   = blockIdx.x * TN;
    int m0   = blockIdx.y * TM;

    float acc[2][8][4];
#pragma unroll
    for (int i = 0; i < 2; ++i)
#pragma unroll
        for (int j = 0; j < 8; ++j)
#pragma unroll
            for (int k = 0; k < 4; ++k) acc[i][j][k] = 0.f;

    load_stage(sb, tid, A, Bm, m0, n0, 0);
    CP_COMMIT();
    load_stage(sb + STAGEB, tid, A, Bm, m0, n0, KC);
    CP_COMMIT();

    int l8  = lane & 7;
    int sel = lane >> 3;         // 0..3
    int g   = lane >> 2;         // 0..7
    int cq  = lane & 3;          // 0..3

#pragma unroll 1
    for (int s = 0; s < NCH; ++s) {
        if (s < NCH - 1) { CP_WAIT(1); } else { CP_WAIT(0); }
        __syncthreads();
        uint32_t aBase = sb + (s & 1) * STAGEB;
        uint32_t bBase = aBase + TILEB;

#pragma unroll
        for (int ks = 0; ks < 4; ++ks) {
            int kb = ks * 32;
            uint32_t af[2][4];
#pragma unroll
            for (int mf = 0; mf < 2; ++mf) {
                // ldmatrix x4: (rows,klo),(rows+8,klo),(rows,khi),(rows+8,khi)
                uint32_t addr = aBase
                    + (wm * 32 + mf * 16 + (sel & 1) * 8 + l8) * ROWB
                    + kb + (sel >> 1) * 16;
                ldsm_x4(af[mf], addr);
            }
            uint32_t bf[8][2];
#pragma unroll
            for (int np = 0; np < 4; ++np) {
                // x4: (nf_even,klo),(nf_even,khi),(nf_odd,klo),(nf_odd,khi)
                uint32_t r4[4];
                uint32_t addr = bBase
                    + (wn * 64 + np * 16 + (sel >> 1) * 8 + l8) * ROWB
                    + kb + (sel & 1) * 16;
                ldsm_x4(r4, addr);
                bf[np * 2 + 0][0] = r4[0]; bf[np * 2 + 0][1] = r4[1];
                bf[np * 2 + 1][0] = r4[2]; bf[np * 2 + 1][1] = r4[3];
            }
#pragma unroll
            for (int mf = 0; mf < 2; ++mf)
#pragma unroll
                for (int nf = 0; nf < 8; ++nf)
                    mma16816(acc[mf][nf], af[mf], bf[nf]);
        }
        __syncthreads();
        if (s + 2 < NCH) {
            load_stage(sb + (s & 1) * STAGEB, tid, A, Bm, m0, n0, (s + 2) * KC);
            CP_COMMIT();
        }
    }

    // ---- epilogue ----
#pragma unroll
    for (int mf = 0; mf < 2; ++mf) {
#pragma unroll
        for (int nf = 0; nf < 8; ++nf) {
            int cn   = n0 + wn * 64 + nf * 8 + cq * 2;
            int row0 = m0 + wm * 32 + mf * 16 + g;
            float2 bb = *(const float2*)(bias + cn);
            float v00 = acc[mf][nf][0] + bb.x, v01 = acc[mf][nf][1] + bb.y;
            float v10 = acc[mf][nf][2] + bb.x, v11 = acc[mf][nf][3] + bb.y;
            if (mode == 0) {
                int t   = cn / CDIM;
                int rem = cn - t * CDIM;
                int hh  = rem >> 5;
                int d   = rem & 31;
                float* basep = (t == 0) ? gQ : (t == 1) ? gK : gV;
#pragma unroll
                for (int rr = 0; rr < 2; ++rr) {
                    int m  = row0 + rr * 8;
                    int w  = m / NTOK;
                    int nn = m - w * NTOK;
                    float* dst = basep + ((size_t)(w * NHEAD + hh) * NTOK + nn) * HD + d;
                    *(float2*)dst = (rr == 0) ? make_float2(v00, v01) : make_float2(v10, v11);
                }
            } else {
#pragma unroll
                for (int rr = 0; rr < 2; ++rr) {
                    int m = row0 + rr * 8;
                    int orow = src_row(m);
                    *(float2*)(outp + (size_t)orow * CDIM + cn) =
                        (rr == 0) ? make_float2(v00, v01) : make_float2(v10, v11);
                }
            }
        }
    }
}

// ---------------- attention (SIMT; emits fp16 for GEMM2) -------------------------
__global__ __launch_bounds__(64) void attn_kernel() {
    const float scale = 0.17677669529663689f;
    int bid = blockIdx.x;
    int w   = bid / NHEAD;
    int h   = bid - w * NHEAD;

    __shared__ float Qs[NTOK][HD];
    __shared__ float Ks[NTOK][HD];
    __shared__ float Vs[NTOK][HD];
    __shared__ float Ps[NTOK][NTOK];
    __shared__ int   rcnt[NTOK];

    int tid = threadIdx.x;
    size_t base = (size_t)(w * NHEAD + h) * NTOK * HD;

    for (int idx = tid; idx < NTOK * HD; idx += 64) {
        ((float*)Qs)[idx] = gQ[base + idx] * scale;
        ((float*)Ks)[idx] = gK[base + idx];
        ((float*)Vs)[idx] = gV[base + idx];
    }
    if (tid < NTOK) {
        int wi = w % NWIN;
        int wy = wi / NWW, wx = wi - wy * NWW;
        int ty = tid / WS, tx = tid - ty * WS;
        int sy = wy * WS + ty, sx = wx * WS + tx;
        int idh = (sy < HDIM - WS) ? 0 : (sy < HDIM - SSH) ? 1 : 2;
        int idw = (sx < WDIM - WS) ? 0 : (sx < WDIM - SSH) ? 1 : 2;
        rcnt[tid] = idh * 3 + idw;
    }
    __syncthreads();

    if (tid < NTOK) {
        float q[HD];
#pragma unroll
        for (int d = 0; d < HD; ++d) q[d] = Qs[tid][d];

        const float* biasRow = gBias + (h * NTOK + tid) * NTOK;
        int myc = rcnt[tid];
        float mx = -1e30f;
        for (int j = 0; j < NTOK; ++j) {
            float s = 0.f;
#pragma unroll
            for (int d = 0; d < HD; d += 4) {
                float4 kv = *(float4*)&Ks[j][d];
                s += q[d] * kv.x + q[d + 1] * kv.y + q[d + 2] * kv.z + q[d + 3] * kv.w;
            }
            s += biasRow[j];
            if (rcnt[j] != myc) s -= 100.0f;
            Ps[tid][j] = s;
            mx = fmaxf(mx, s);
        }
        float sum = 0.f;
        for (int j = 0; j < NTOK; ++j) {
            float e = __expf(Ps[tid][j] - mx);
            Ps[tid][j] = e;
            sum += e;
        }
        float inv = 1.0f / sum;

        float o[HD] = {};
        for (int j = 0; j < NTOK; ++j) {
            float pj = Ps[tid][j] * inv;
#pragma unroll
            for (int d = 0; d < HD; d += 4) {
                float4 vv = *(float4*)&Vs[j][d];
                o[d]     += pj * vv.x;
                o[d + 1] += pj * vv.y;
                o[d + 2] += pj * vv.z;
                o[d + 3] += pj * vv.w;
            }
        }
        size_t dstoff = (size_t)(w * NTOK + tid) * CDIM + h * HD;
#pragma unroll
        for (int d = 0; d < HD; d += 4) {
            __half2 h0 = __floats2half2_rn(o[d], o[d + 1]);
            __half2 h1 = __floats2half2_rn(o[d + 2], o[d + 3]);
            *(uint2*)(gOh + dstoff + d) = make_uint2(*(uint32_t*)&h0, *(uint32_t*)&h1);
        }
    }
}

// ---------------- launch ----------------
extern "C" void kernel_launch(void* const* d_in, const int* in_sizes, int n_in,
                              void* d_out, int out_size) {
    (void)in_sizes; (void)n_in; (void)out_size;
    const float* x      = (const float*)d_in[0];
    const float* qkv_w  = (const float*)d_in[1];
    const float* qkv_b  = (const float*)d_in[2];
    const float* proj_w = (const float*)d_in[3];
    const float* proj_b = (const float*)d_in[4];
    const float* rpt    = (const float*)d_in[5];
    float* out = (float*)d_out;

    cudaFuncSetAttribute(mma_gemm, cudaFuncAttributeMaxDynamicSharedMemorySize, SMEM_SZ);

    __half *pXh, *pOh, *pWh, *pPh;
    cudaGetSymbolAddress((void**)&pXh, gXh);
    cudaGetSymbolAddress((void**)&pOh, gOh);
    cudaGetSymbolAddress((void**)&pWh, gWh);
    cudaGetSymbolAddress((void**)&pPh, gPh);

    bias_kernel<<<(NHEAD * NTOK * NTOK + 255) / 256, 256>>>(rpt);
    gather_h<<<(MROWS * (CDIM / 4) + 255) / 256, 256>>>(x);
    wsplit_h<<<(QKVN * CDIM + 255) / 256, 256>>>(qkv_w, pWh, QKVN, CDIM);
    wsplit_h<<<(CDIM * CDIM + 255) / 256, 256>>>(proj_w, pPh, CDIM, CDIM);

    dim3 g1(QKVN / TN, MROWS / TM);   // (9, 784)
    mma_gemm<<<g1, 256, SMEM_SZ>>>(pXh, pWh, qkv_b, nullptr, 0);

    attn_kernel<<<BW * NHEAD, 64>>>();

    dim3 g2(CDIM / TN, MROWS / TM);   // (3, 784)
    mma_gemm<<<g2, 256, SMEM_SZ>>>(pOh, pPh, proj_b, out, 1);
}

// round 6
// speedup vs baseline: 3.9137x; 1.0901x over previous
#include <cuda_runtime.h>
#include <cuda_fp16.h>
#include <cstdint>

// ---------------- problem constants ----------------
#define B_    8
#define HDIM  112
#define WDIM  112
#define CDIM  384
#define NHEAD 12
#define HD    32
#define WS    7
#define SSH   3
#define NTOK  49
#define NWH   16
#define NWW   16
#define NWIN  256
#define BW    (B_ * NWIN)          // 2048 windows
#define MROWS (BW * NTOK)          // 100352
#define QKVN  (3 * CDIM)           // 1152
#define BSTRIDE 2432               // padded bias row stride (16B-aligned float4 rows)

// GEMM tiling (HMMA mma.sync, fp16 single pass)
#define TM   128
#define TN   128
#define KC   64
#define NCH  (CDIM / KC)           // 6
#define ROWB 144
#define TILEB (128 * ROWB)         // 18432
#define STAGEB (2 * TILEB)         // 36864
#define SMEM_SZ (2 * STAGEB)       // 73728

// ---------------- scratch ----------------
__device__ float gQ[(size_t)BW * NHEAD * NTOK * HD];
__device__ float gK[(size_t)BW * NHEAD * NTOK * HD];
__device__ float gV[(size_t)BW * NHEAD * NTOK * HD];
__device__ __half gXh[(size_t)MROWS * CDIM];
__device__ __half gOh[(size_t)MROWS * CDIM];
__device__ __half gWh[(size_t)QKVN * CDIM];
__device__ __half gPh[(size_t)CDIM * CDIM];
__device__ float gBias[NHEAD * BSTRIDE];

// ---------------- helpers ----------------
#define CP_ASYNC16(dst, src) \
    asm volatile("cp.async.cg.shared.global [%0], [%1], 16;" :: "r"(dst), "l"(src))
#define CP_COMMIT() asm volatile("cp.async.commit_group;" ::: "memory")
#define CP_WAIT(n)  asm volatile("cp.async.wait_group %0;" :: "n"(n) : "memory")

__device__ __forceinline__ uint32_t smem_u32(const void* p) {
    uint32_t a;
    asm("{ .reg .u64 t; cvta.to.shared.u64 t, %1; cvt.u32.u64 %0, t; }" : "=r"(a) : "l"(p));
    return a;
}
__device__ __forceinline__ void ldsm_x4(uint32_t* r, uint32_t addr) {
    asm volatile("ldmatrix.sync.aligned.m8n8.x4.shared.b16 {%0,%1,%2,%3}, [%4];"
                 : "=r"(r[0]), "=r"(r[1]), "=r"(r[2]), "=r"(r[3]) : "r"(addr));
}
__device__ __forceinline__ void mma16816(float* c, const uint32_t* a, const uint32_t* b) {
    asm volatile(
        "mma.sync.aligned.m16n8k16.row.col.f32.f16.f16.f32 "
        "{%0,%1,%2,%3}, {%4,%5,%6,%7}, {%8,%9}, {%0,%1,%2,%3};"
        : "+f"(c[0]), "+f"(c[1]), "+f"(c[2]), "+f"(c[3])
        : "r"(a[0]), "r"(a[1]), "r"(a[2]), "r"(a[3]), "r"(b[0]), "r"(b[1]));
}

// ---------------- shift/window row mapping ----------------
__device__ __forceinline__ int src_row(int m) {
    int w  = m / NTOK;
    int n  = m - w * NTOK;
    int b  = w / NWIN;
    int wi = w - b * NWIN;
    int wy = wi / NWW;
    int wx = wi - wy * NWW;
    int ty = n / WS;
    int tx = n - ty * WS;
    int sy = wy * WS + ty;
    int sx = wx * WS + tx;
    int oy = sy + SSH; if (oy >= HDIM) oy -= HDIM;
    int ox = sx + SSH; if (ox >= WDIM) ox -= WDIM;
    return (b * HDIM + oy) * WDIM + ox;
}

// ---------------- prep kernels ----------------
__global__ void bias_kernel(const float* __restrict__ rel_pos_table) {
    int idx = blockIdx.x * blockDim.x + threadIdx.x;
    if (idx >= NHEAD * NTOK * NTOK) return;
    int h = idx / (NTOK * NTOK);
    int r = idx - h * (NTOK * NTOK);
    int i = r / NTOK;
    int j = r - i * NTOK;
    int ci = 13 * (i / 7) + (i % 7);
    int jr = 48 - j;
    int cj = 13 * (jr / 7) + (jr % 7);
    gBias[h * BSTRIDE + r] = rel_pos_table[(ci + cj) * NHEAD + h];
}

__global__ __launch_bounds__(256) void gather_h(const float* __restrict__ x) {
    int t = blockIdx.x * blockDim.x + threadIdx.x;
    if (t >= MROWS * (CDIM / 4)) return;
    int m = t / (CDIM / 4);
    int q = t - m * (CDIM / 4);
    float4 v = *(const float4*)(x + (size_t)src_row(m) * CDIM + q * 4);
    __half2 h0 = __floats2half2_rn(v.x, v.y);
    __half2 h1 = __floats2half2_rn(v.z, v.w);
    *(uint2*)(gXh + (size_t)m * CDIM + q * 4) =
        make_uint2(*(uint32_t*)&h0, *(uint32_t*)&h1);
}

__global__ void wsplit_h(const float* __restrict__ src, __half* dst, int N, int K) {
    int t = blockIdx.x * blockDim.x + threadIdx.x;
    if (t >= N * K) return;
    int n = t / K;
    int k = t - n * K;
    dst[t] = __float2half_rn(src[(size_t)k * N + n]);
}

// ---------------- HMMA GEMM ----------------
__device__ __forceinline__ void load_stage(uint32_t sbuf, int tid,
        const __half* A, const __half* Bm, int m0, int n0, int k0) {
#pragma unroll
    for (int i = 0; i < 8; ++i) {
        int q    = tid + i * 256;
        int tile = q >> 10;
        int idx  = q & 1023;
        int r    = idx >> 3;
        int c    = idx & 7;
        const __half* srcp = (tile == 0)
            ? A  + (size_t)(m0 + r) * CDIM + k0 + c * 8
            : Bm + (size_t)(n0 + r) * CDIM + k0 + c * 8;
        uint32_t dst = sbuf + tile * TILEB + r * ROWB + c * 16;
        CP_ASYNC16(dst, srcp);
    }
}

__global__ __launch_bounds__(256, 2) void mma_gemm(
        const __half* __restrict__ A, const __half* __restrict__ Bm,
        const float* __restrict__ bias, float* __restrict__ outp, int mode) {
    extern __shared__ char smem[];
    uint32_t sb = smem_u32(smem);

    int tid  = threadIdx.x;
    int wid  = tid >> 5;
    int lane = tid & 31;
    int wm   = wid & 3;
    int wn   = wid >> 2;
    int n0   = blockIdx.x * TN;
    int m0   = blockIdx.y * TM;

    float acc[2][8][4];
#pragma unroll
    for (int i = 0; i < 2; ++i)
#pragma unroll
        for (int j = 0; j < 8; ++j)
#pragma unroll
            for (int k = 0; k < 4; ++k) acc[i][j][k] = 0.f;

    load_stage(sb, tid, A, Bm, m0, n0, 0);
    CP_COMMIT();
    load_stage(sb + STAGEB, tid, A, Bm, m0, n0, KC);
    CP_COMMIT();

    int l8  = lane & 7;
    int sel = lane >> 3;
    int g   = lane >> 2;
    int cq  = lane & 3;

#pragma unroll 1
    for (int s = 0; s < NCH; ++s) {
        if (s < NCH - 1) { CP_WAIT(1); } else { CP_WAIT(0); }
        __syncthreads();
        uint32_t aBase = sb + (s & 1) * STAGEB;
        uint32_t bBase = aBase + TILEB;

#pragma unroll
        for (int ks = 0; ks < 4; ++ks) {
            int kb = ks * 32;
            uint32_t af[2][4];
#pragma unroll
            for (int mf = 0; mf < 2; ++mf) {
                uint32_t addr = aBase
                    + (wm * 32 + mf * 16 + (sel & 1) * 8 + l8) * ROWB
                    + kb + (sel >> 1) * 16;
                ldsm_x4(af[mf], addr);
            }
            uint32_t bf[8][2];
#pragma unroll
            for (int np = 0; np < 4; ++np) {
                uint32_t r4[4];
                uint32_t addr = bBase
                    + (wn * 64 + np * 16 + (sel >> 1) * 8 + l8) * ROWB
                    + kb + (sel & 1) * 16;
                ldsm_x4(r4, addr);
                bf[np * 2 + 0][0] = r4[0]; bf[np * 2 + 0][1] = r4[1];
                bf[np * 2 + 1][0] = r4[2]; bf[np * 2 + 1][1] = r4[3];
            }
#pragma unroll
            for (int mf = 0; mf < 2; ++mf)
#pragma unroll
                for (int nf = 0; nf < 8; ++nf)
                    mma16816(acc[mf][nf], af[mf], bf[nf]);
        }
        __syncthreads();
        if (s + 2 < NCH) {
            load_stage(sb + (s & 1) * STAGEB, tid, A, Bm, m0, n0, (s + 2) * KC);
            CP_COMMIT();
        }
    }

    // ---- epilogue ----
#pragma unroll
    for (int mf = 0; mf < 2; ++mf) {
#pragma unroll
        for (int nf = 0; nf < 8; ++nf) {
            int cn   = n0 + wn * 64 + nf * 8 + cq * 2;
            int row0 = m0 + wm * 32 + mf * 16 + g;
            float2 bb = *(const float2*)(bias + cn);
            float v00 = acc[mf][nf][0] + bb.x, v01 = acc[mf][nf][1] + bb.y;
            float v10 = acc[mf][nf][2] + bb.x, v11 = acc[mf][nf][3] + bb.y;
            if (mode == 0) {
                int t   = cn / CDIM;
                int rem = cn - t * CDIM;
                int hh  = rem >> 5;
                int d   = rem & 31;
                float* basep = (t == 0) ? gQ : (t == 1) ? gK : gV;
#pragma unroll
                for (int rr = 0; rr < 2; ++rr) {
                    int m  = row0 + rr * 8;
                    int w  = m / NTOK;
                    int nn = m - w * NTOK;
                    float* dst = basep + ((size_t)(w * NHEAD + hh) * NTOK + nn) * HD + d;
                    *(float2*)dst = (rr == 0) ? make_float2(v00, v01) : make_float2(v10, v11);
                }
            } else {
#pragma unroll
                for (int rr = 0; rr < 2; ++rr) {
                    int m = row0 + rr * 8;
                    int orow = src_row(m);
                    *(float2*)(outp + (size_t)orow * CDIM + cn) =
                        (rr == 0) ? make_float2(v00, v01) : make_float2(v10, v11);
                }
            }
        }
    }
}

// ---------------- attention: register-resident scores, 2-pass online softmax ----
__global__ __launch_bounds__(64) void attn_kernel() {
    const float scale = 0.17677669529663689f;
    int bid = blockIdx.x;
    int w   = bid / NHEAD;
    int h   = bid - w * NHEAD;

    __shared__ float Ks[NTOK][HD];
    __shared__ float Vs[NTOK][HD];
    __shared__ float Bs[NTOK * NTOK];   // 9604 B
    __shared__ int   rcnt[NTOK];

    int tid = threadIdx.x;
    size_t base = (size_t)(w * NHEAD + h) * NTOK * HD;

    // cooperative loads (float4)
    const float4* k4 = (const float4*)(gK + base);
    const float4* v4 = (const float4*)(gV + base);
#pragma unroll
    for (int i = 0; i < 7; ++i) {
        int idx = tid + i * 64;               // 392 float4 total
        if (idx < NTOK * HD / 4) {
            ((float4*)Ks)[idx] = k4[idx];
            ((float4*)Vs)[idx] = v4[idx];
        }
    }
    const float4* b4 = (const float4*)(gBias + h * BSTRIDE);
#pragma unroll
    for (int i = 0; i < 10; ++i) {
        int idx = tid + i * 64;               // 600 float4 = 2400 floats
        if (idx < 600) ((float4*)Bs)[idx] = b4[idx];
    }
    if (tid == 0) Bs[2400] = gBias[h * BSTRIDE + 2400];
    if (tid < NTOK) {
        int wi = w % NWIN;
        int wy = wi / NWW, wx = wi - wy * NWW;
        int ty = tid / WS, tx = tid - ty * WS;
        int sy = wy * WS + ty, sx = wx * WS + tx;
        int idh = (sy < HDIM - WS) ? 0 : (sy < HDIM - SSH) ? 1 : 2;
        int idw = (sx < WDIM - WS) ? 0 : (sx < WDIM - SSH) ? 1 : 2;
        rcnt[tid] = idh * 3 + idw;
    }
    __syncthreads();

    if (tid < NTOK) {
        float q[HD];
        const float4* q4 = (const float4*)(gQ + base + (size_t)tid * HD);
#pragma unroll
        for (int d = 0; d < 8; ++d) {
            float4 t = q4[d];
            q[d * 4 + 0] = t.x * scale;
            q[d * 4 + 1] = t.y * scale;
            q[d * 4 + 2] = t.z * scale;
            q[d * 4 + 3] = t.w * scale;
        }
        int myc = rcnt[tid];
        const float* brow = Bs + tid * NTOK;

        float scores[NTOK];
        float mx = -1e30f;
#pragma unroll
        for (int j = 0; j < NTOK; ++j) {
            float s0 = 0.f, s1 = 0.f, s2 = 0.f, s3 = 0.f;
#pragma unroll
            for (int d = 0; d < HD; d += 4) {
                float4 kv = *(float4*)&Ks[j][d];
                s0 += q[d]     * kv.x;
                s1 += q[d + 1] * kv.y;
                s2 += q[d + 2] * kv.z;
                s3 += q[d + 3] * kv.w;
            }
            float s = (s0 + s1) + (s2 + s3) + brow[j];
            if (rcnt[j] != myc) s -= 100.0f;
            scores[j] = s;
            mx = fmaxf(mx, s);
        }

        float sum = 0.f;
        float o[HD] = {};
#pragma unroll
        for (int j = 0; j < NTOK; ++j) {
            float e = __expf(scores[j] - mx);
            sum += e;
#pragma unroll
            for (int d = 0; d < HD; d += 4) {
                float4 vv = *(float4*)&Vs[j][d];
                o[d]     += e * vv.x;
                o[d + 1] += e * vv.y;
                o[d + 2] += e * vv.z;
                o[d + 3] += e * vv.w;
            }
        }
        float inv = 1.0f / sum;

        size_t dstoff = (size_t)(w * NTOK + tid) * CDIM + h * HD;
#pragma unroll
        for (int d = 0; d < HD; d += 4) {
            __half2 h0 = __floats2half2_rn(o[d] * inv, o[d + 1] * inv);
            __half2 h1 = __floats2half2_rn(o[d + 2] * inv, o[d + 3] * inv);
            *(uint2*)(gOh + dstoff + d) = make_uint2(*(uint32_t*)&h0, *(uint32_t*)&h1);
        }
    }
}

// ---------------- launch ----------------
extern "C" void kernel_launch(void* const* d_in, const int* in_sizes, int n_in,
                              void* d_out, int out_size) {
    (void)in_sizes; (void)n_in; (void)out_size;
    const float* x      = (const float*)d_in[0];
    const float* qkv_w  = (const float*)d_in[1];
    const float* qkv_b  = (const float*)d_in[2];
    const float* proj_w = (const float*)d_in[3];
    const float* proj_b = (const float*)d_in[4];
    const float* rpt    = (const float*)d_in[5];
    float* out = (float*)d_out;

    cudaFuncSetAttribute(mma_gemm, cudaFuncAttributeMaxDynamicSharedMemorySize, SMEM_SZ);

    __half *pXh, *pOh, *pWh, *pPh;
    cudaGetSymbolAddress((void**)&pXh, gXh);
    cudaGetSymbolAddress((void**)&pOh, gOh);
    cudaGetSymbolAddress((void**)&pWh, gWh);
    cudaGetSymbolAddress((void**)&pPh, gPh);

    bias_kernel<<<(NHEAD * NTOK * NTOK + 255) / 256, 256>>>(rpt);
    gather_h<<<(MROWS * (CDIM / 4) + 255) / 256, 256>>>(x);
    wsplit_h<<<(QKVN * CDIM + 255) / 256, 256>>>(qkv_w, pWh, QKVN, CDIM);
    wsplit_h<<<(CDIM * CDIM + 255) / 256, 256>>>(proj_w, pPh, CDIM, CDIM);

    dim3 g1(QKVN / TN, MROWS / TM);   // (9, 784)
    mma_gemm<<<g1, 256, SMEM_SZ>>>(pXh, pWh, qkv_b, nullptr, 0);

    attn_kernel<<<BW * NHEAD, 64>>>();

    dim3 g2(CDIM / TN, MROWS / TM);   // (3, 784)
    mma_gemm<<<g2, 256, SMEM_SZ>>>(pOh, pPh, proj_b, out, 1);
}

// round 7
// speedup vs baseline: 5.4403x; 1.3901x over previous
#include <cuda_runtime.h>
#include <cuda_fp16.h>
#include <cstdint>

// ---------------- problem constants ----------------
#define B_    8
#define HDIM  112
#define WDIM  112
#define CDIM  384
#define NHEAD 12
#define HD    32
#define WS    7
#define SSH   3
#define NTOK  49
#define NPAD  64
#define NWH   16
#define NWW   16
#define NWIN  256
#define BW    (B_ * NWIN)          // 2048 windows
#define MROWS (BW * NTOK)          // 100352
#define QKVN  (3 * CDIM)           // 1152
#define BSTRIDE 2432

// GEMM tiling (HMMA mma.sync fp16)
#define TM   128
#define TN   128
#define KC   64
#define NCH  (CDIM / KC)           // 6
#define ROWB 144
#define TILEB (128 * ROWB)
#define STAGEB (2 * TILEB)
#define SMEM_SZ (2 * STAGEB)       // 73728

// ---------------- scratch ----------------
__device__ __half gQh[(size_t)BW * NHEAD * NPAD * HD];   // pads stay zero
__device__ __half gKh[(size_t)BW * NHEAD * NPAD * HD];
__device__ __half gVh[(size_t)BW * NHEAD * NPAD * HD];
__device__ __half gXh[(size_t)MROWS * CDIM];
__device__ __half gOh[(size_t)MROWS * CDIM];
__device__ __half gWh[(size_t)QKVN * CDIM];
__device__ __half gPh[(size_t)CDIM * CDIM];
__device__ float gBias[NHEAD * BSTRIDE];

// ---------------- helpers ----------------
#define CP_ASYNC16(dst, src) \
    asm volatile("cp.async.cg.shared.global [%0], [%1], 16;" :: "r"(dst), "l"(src))
#define CP_COMMIT() asm volatile("cp.async.commit_group;" ::: "memory")
#define CP_WAIT(n)  asm volatile("cp.async.wait_group %0;" :: "n"(n) : "memory")

__device__ __forceinline__ uint32_t smem_u32(const void* p) {
    uint32_t a;
    asm("{ .reg .u64 t; cvta.to.shared.u64 t, %1; cvt.u32.u64 %0, t; }" : "=r"(a) : "l"(p));
    return a;
}
__device__ __forceinline__ void ldsm_x4(uint32_t* r, uint32_t addr) {
    asm volatile("ldmatrix.sync.aligned.m8n8.x4.shared.b16 {%0,%1,%2,%3}, [%4];"
                 : "=r"(r[0]), "=r"(r[1]), "=r"(r[2]), "=r"(r[3]) : "r"(addr));
}
__device__ __forceinline__ void mma16816(float* c, const uint32_t* a, const uint32_t* b) {
    asm volatile(
        "mma.sync.aligned.m16n8k16.row.col.f32.f16.f16.f32 "
        "{%0,%1,%2,%3}, {%4,%5,%6,%7}, {%8,%9}, {%0,%1,%2,%3};"
        : "+f"(c[0]), "+f"(c[1]), "+f"(c[2]), "+f"(c[3])
        : "r"(a[0]), "r"(a[1]), "r"(a[2]), "r"(a[3]), "r"(b[0]), "r"(b[1]));
}
__device__ __forceinline__ uint32_t h2pack(float a, float b) {
    __half2 h = __floats2half2_rn(a, b);
    return *reinterpret_cast<uint32_t*>(&h);
}

// ---------------- shift/window row mapping ----------------
__device__ __forceinline__ int src_row(int m) {
    int w  = m / NTOK;
    int n  = m - w * NTOK;
    int b  = w / NWIN;
    int wi = w - b * NWIN;
    int wy = wi / NWW;
    int wx = wi - wy * NWW;
    int ty = n / WS;
    int tx = n - ty * WS;
    int sy = wy * WS + ty;
    int sx = wx * WS + tx;
    int oy = sy + SSH; if (oy >= HDIM) oy -= HDIM;
    int ox = sx + SSH; if (ox >= WDIM) ox -= WDIM;
    return (b * HDIM + oy) * WDIM + ox;
}

// ---------------- prep kernels ----------------
__global__ void bias_kernel(const float* __restrict__ rel_pos_table) {
    int idx = blockIdx.x * blockDim.x + threadIdx.x;
    if (idx >= NHEAD * NTOK * NTOK) return;
    int h = idx / (NTOK * NTOK);
    int r = idx - h * (NTOK * NTOK);
    int i = r / NTOK;
    int j = r - i * NTOK;
    int ci = 13 * (i / 7) + (i % 7);
    int jr = 48 - j;
    int cj = 13 * (jr / 7) + (jr % 7);
    gBias[h * BSTRIDE + r] = rel_pos_table[(ci + cj) * NHEAD + h];
}

__global__ __launch_bounds__(256) void gather_h(const float* __restrict__ x) {
    int t = blockIdx.x * blockDim.x + threadIdx.x;
    if (t >= MROWS * (CDIM / 4)) return;
    int m = t / (CDIM / 4);
    int q = t - m * (CDIM / 4);
    float4 v = *(const float4*)(x + (size_t)src_row(m) * CDIM + q * 4);
    *(uint2*)(gXh + (size_t)m * CDIM + q * 4) =
        make_uint2(h2pack(v.x, v.y), h2pack(v.z, v.w));
}

__global__ void wsplit_h(const float* __restrict__ src, __half* dst, int N, int K) {
    int t = blockIdx.x * blockDim.x + threadIdx.x;
    if (t >= N * K) return;
    int n = t / K;
    int k = t - n * K;
    dst[t] = __float2half_rn(src[(size_t)k * N + n]);
}

// ---------------- HMMA GEMM ----------------
__device__ __forceinline__ void load_stage(uint32_t sbuf, int tid,
        const __half* A, const __half* Bm, int m0, int n0, int k0) {
#pragma unroll
    for (int i = 0; i < 8; ++i) {
        int q    = tid + i * 256;
        int tile = q >> 10;
        int idx  = q & 1023;
        int r    = idx >> 3;
        int c    = idx & 7;
        const __half* srcp = (tile == 0)
            ? A  + (size_t)(m0 + r) * CDIM + k0 + c * 8
            : Bm + (size_t)(n0 + r) * CDIM + k0 + c * 8;
        uint32_t dst = sbuf + tile * TILEB + r * ROWB + c * 16;
        CP_ASYNC16(dst, srcp);
    }
}

__global__ __launch_bounds__(256, 2) void mma_gemm(
        const __half* __restrict__ A, const __half* __restrict__ Bm,
        const float* __restrict__ bias, float* __restrict__ outp, int mode) {
    extern __shared__ char smem[];
    uint32_t sb = smem_u32(smem);

    int tid  = threadIdx.x;
    int wid  = tid >> 5;
    int lane = tid & 31;
    int wm   = wid & 3;
    int wn   = wid >> 2;
    int n0   = blockIdx.x * TN;
    int m0   = blockIdx.y * TM;

    float acc[2][8][4];
#pragma unroll
    for (int i = 0; i < 2; ++i)
#pragma unroll
        for (int j = 0; j < 8; ++j)
#pragma unroll
            for (int k = 0; k < 4; ++k) acc[i][j][k] = 0.f;

    load_stage(sb, tid, A, Bm, m0, n0, 0);
    CP_COMMIT();
    load_stage(sb + STAGEB, tid, A, Bm, m0, n0, KC);
    CP_COMMIT();

    int l8  = lane & 7;
    int sel = lane >> 3;
    int g   = lane >> 2;
    int cq  = lane & 3;

#pragma unroll 1
    for (int s = 0; s < NCH; ++s) {
        if (s < NCH - 1) { CP_WAIT(1); } else { CP_WAIT(0); }
        __syncthreads();
        uint32_t aBase = sb + (s & 1) * STAGEB;
        uint32_t bBase = aBase + TILEB;

#pragma unroll
        for (int ks = 0; ks < 4; ++ks) {
            int kb = ks * 32;
            uint32_t af[2][4];
#pragma unroll
            for (int mf = 0; mf < 2; ++mf) {
                uint32_t addr = aBase
                    + (wm * 32 + mf * 16 + (sel & 1) * 8 + l8) * ROWB
                    + kb + (sel >> 1) * 16;
                ldsm_x4(af[mf], addr);
            }
            uint32_t bf[8][2];
#pragma unroll
            for (int np = 0; np < 4; ++np) {
                uint32_t r4[4];
                uint32_t addr = bBase
                    + (wn * 64 + np * 16 + (sel >> 1) * 8 + l8) * ROWB
                    + kb + (sel & 1) * 16;
                ldsm_x4(r4, addr);
                bf[np * 2 + 0][0] = r4[0]; bf[np * 2 + 0][1] = r4[1];
                bf[np * 2 + 1][0] = r4[2]; bf[np * 2 + 1][1] = r4[3];
            }
#pragma unroll
            for (int mf = 0; mf < 2; ++mf)
#pragma unroll
                for (int nf = 0; nf < 8; ++nf)
                    mma16816(acc[mf][nf], af[mf], bf[nf]);
        }
        __syncthreads();
        if (s + 2 < NCH) {
            load_stage(sb + (s & 1) * STAGEB, tid, A, Bm, m0, n0, (s + 2) * KC);
            CP_COMMIT();
        }
    }

    const float qscale = 0.17677669529663689f;
#pragma unroll
    for (int mf = 0; mf < 2; ++mf) {
#pragma unroll
        for (int nf = 0; nf < 8; ++nf) {
            int cn   = n0 + wn * 64 + nf * 8 + cq * 2;
            int row0 = m0 + wm * 32 + mf * 16 + g;
            float2 bb = *(const float2*)(bias + cn);
            float v00 = acc[mf][nf][0] + bb.x, v01 = acc[mf][nf][1] + bb.y;
            float v10 = acc[mf][nf][2] + bb.x, v11 = acc[mf][nf][3] + bb.y;
            if (mode == 0) {
                int t   = cn / CDIM;
                int rem = cn - t * CDIM;
                int hh  = rem >> 5;
                int d   = rem & 31;
                __half* basep = (t == 0) ? gQh : (t == 1) ? gKh : gVh;
                float sc = (t == 0) ? qscale : 1.0f;
#pragma unroll
                for (int rr = 0; rr < 2; ++rr) {
                    int m  = row0 + rr * 8;
                    int w  = m / NTOK;
                    int nn = m - w * NTOK;
                    uint32_t hv = (rr == 0) ? h2pack(v00 * sc, v01 * sc)
                                            : h2pack(v10 * sc, v11 * sc);
                    *(uint32_t*)(basep + ((size_t)(w * NHEAD + hh) * NPAD + nn) * HD + d) = hv;
                }
            } else {
#pragma unroll
                for (int rr = 0; rr < 2; ++rr) {
                    int m = row0 + rr * 8;
                    int orow = src_row(m);
                    *(float2*)(outp + (size_t)orow * CDIM + cn) =
                        (rr == 0) ? make_float2(v00, v01) : make_float2(v10, v11);
                }
            }
        }
    }
}

// ---------------- attention: HMMA flash-style, one (w,h) per 64-thread block -----
#define QSTR 40      // Qs/Ks row stride in halfs (80 B)
#define VSTR 72      // Vt row stride in halfs (144 B)

__global__ __launch_bounds__(64) void attn_mma() {
    __shared__ __half Qs[NPAD * QSTR];
    __shared__ __half Ks[NPAD * QSTR];
    __shared__ __half Vt[HD * VSTR];
    __shared__ float  Bs[NTOK * NTOK];
    __shared__ int    rcnt[NPAD];

    int bid = blockIdx.x;
    int w   = bid / NHEAD;
    int h   = bid - w * NHEAD;
    int tid  = threadIdx.x;
    int wi   = tid >> 5;
    int lane = tid & 31;
    int g    = lane >> 2;
    int cq   = lane & 3;
    int l8   = lane & 7;
    int sel  = lane >> 3;

    size_t base = (size_t)(w * NHEAD + h) * NPAD * HD;
    const uint4* q4 = (const uint4*)(gQh + base);
    const uint4* k4 = (const uint4*)(gKh + base);
    const uint4* v4 = (const uint4*)(gVh + base);

    // Q, K into smem (stride QSTR); 256 uint4 each
#pragma unroll
    for (int i = 0; i < 4; ++i) {
        int idx = tid + i * 64;
        int r = idx >> 2, c = idx & 3;
        *(uint4*)(Qs + r * QSTR + c * 8) = q4[idx];
        *(uint4*)(Ks + r * QSTR + c * 8) = k4[idx];
    }
    // V transposed into Vt[d][j]
#pragma unroll
    for (int i = 0; i < 4; ++i) {
        int idx = tid + i * 64;
        int j = idx >> 2, c = idx & 3;
        uint4 u = v4[idx];
        __half hv[8];
        *(uint2*)&hv[0] = make_uint2(u.x, u.y);
        *(uint2*)&hv[4] = make_uint2(u.z, u.w);
#pragma unroll
        for (int e = 0; e < 8; ++e) Vt[(c * 8 + e) * VSTR + j] = hv[e];
    }
    // bias
    const float4* b4 = (const float4*)(gBias + h * BSTRIDE);
#pragma unroll
    for (int i = 0; i < 10; ++i) {
        int idx = tid + i * 64;
        if (idx < 600) ((float4*)Bs)[idx] = b4[idx];
    }
    if (tid == 0) Bs[2400] = gBias[h * BSTRIDE + 2400];
    // region ids
    if (tid < NPAD) {
        int r = 0;
        if (tid < NTOK) {
            int wpos = w % NWIN;
            int wy = wpos / NWW, wx = wpos - wy * NWW;
            int ty = tid / WS, tx = tid - ty * WS;
            int sy = wy * WS + ty, sx = wx * WS + tx;
            int idh = (sy < HDIM - WS) ? 0 : (sy < HDIM - SSH) ? 1 : 2;
            int idw = (sx < WDIM - WS) ? 0 : (sx < WDIM - SSH) ? 1 : 2;
            r = idh * 3 + idw;
        }
        rcnt[tid] = r;
    }
    __syncthreads();

    uint32_t qsb = smem_u32(Qs);
    uint32_t ksb = smem_u32(Ks);
    uint32_t vtb = smem_u32(Vt);

    // ---- QK^T: scores s[2][8][4] (rows wi*32 + mf*16 + {g, g+8}, cols 8nf+2cq+{0,1})
    float s[2][8][4];
#pragma unroll
    for (int i = 0; i < 2; ++i)
#pragma unroll
        for (int j = 0; j < 8; ++j)
#pragma unroll
            for (int k = 0; k < 4; ++k) s[i][j][k] = 0.f;

#pragma unroll
    for (int ks = 0; ks < 2; ++ks) {
        int kb = ks * 32;                       // bytes (16 halfs)
        uint32_t af[2][4];
#pragma unroll
        for (int mf = 0; mf < 2; ++mf) {
            uint32_t addr = qsb
                + ((wi * 32 + mf * 16 + (sel & 1) * 8 + l8) * QSTR) * 2
                + kb + (sel >> 1) * 16;
            ldsm_x4(af[mf], addr);
        }
        uint32_t bf[8][2];
#pragma unroll
        for (int np = 0; np < 4; ++np) {
            uint32_t r4[4];
            uint32_t addr = ksb
                + ((np * 16 + (sel >> 1) * 8 + l8) * QSTR) * 2
                + kb + (sel & 1) * 16;
            ldsm_x4(r4, addr);
            bf[np * 2 + 0][0] = r4[0]; bf[np * 2 + 0][1] = r4[1];
            bf[np * 2 + 1][0] = r4[2]; bf[np * 2 + 1][1] = r4[3];
        }
#pragma unroll
        for (int mf = 0; mf < 2; ++mf)
#pragma unroll
            for (int nf = 0; nf < 8; ++nf)
                mma16816(s[mf][nf], af[mf], bf[nf]);
    }

    // ---- softmax in fragment layout ----
    float inv[2][2];
#pragma unroll
    for (int mf = 0; mf < 2; ++mf) {
        int rA = wi * 32 + mf * 16 + g;
        int rB = rA + 8;
        int rAc = rA < NTOK ? rA : NTOK - 1;
        int rBc = rB < NTOK ? rB : NTOK - 1;
        int cA = rcnt[rAc], cB = rcnt[rBc];
        float mxA = -1e30f, mxB = -1e30f;
#pragma unroll
        for (int nf = 0; nf < 8; ++nf) {
#pragma unroll
            for (int e = 0; e < 2; ++e) {
                int j  = nf * 8 + cq * 2 + e;
                int jj = j < NTOK ? j : NTOK - 1;
                float mk = (rcnt[jj] != cA) ? -100.f : 0.f;
                float tA = s[mf][nf][e] + Bs[rAc * NTOK + jj] + mk;
                s[mf][nf][e] = (j < NTOK) ? tA : -1e30f;
                mxA = fmaxf(mxA, s[mf][nf][e]);
                float mk2 = (rcnt[jj] != cB) ? -100.f : 0.f;
                float tB = s[mf][nf][2 + e] + Bs[rBc * NTOK + jj] + mk2;
                s[mf][nf][2 + e] = (j < NTOK) ? tB : -1e30f;
                mxB = fmaxf(mxB, s[mf][nf][2 + e]);
            }
        }
        mxA = fmaxf(mxA, __shfl_xor_sync(0xffffffff, mxA, 1));
        mxA = fmaxf(mxA, __shfl_xor_sync(0xffffffff, mxA, 2));
        mxB = fmaxf(mxB, __shfl_xor_sync(0xffffffff, mxB, 1));
        mxB = fmaxf(mxB, __shfl_xor_sync(0xffffffff, mxB, 2));
        float smA = 0.f, smB = 0.f;
#pragma unroll
        for (int nf = 0; nf < 8; ++nf) {
#pragma unroll
            for (int e = 0; e < 2; ++e) {
                float eA = __expf(s[mf][nf][e] - mxA);
                float eB = __expf(s[mf][nf][2 + e] - mxB);
                s[mf][nf][e] = eA;  smA += eA;
                s[mf][nf][2 + e] = eB;  smB += eB;
            }
        }
        smA += __shfl_xor_sync(0xffffffff, smA, 1);
        smA += __shfl_xor_sync(0xffffffff, smA, 2);
        smB += __shfl_xor_sync(0xffffffff, smB, 1);
        smB += __shfl_xor_sync(0xffffffff, smB, 2);
        inv[mf][0] = 1.0f / smA;
        inv[mf][1] = 1.0f / smB;
    }

    // ---- P (fp16 A-fragments) @ V ----
    float o[2][4][4];
#pragma unroll
    for (int i = 0; i < 2; ++i)
#pragma unroll
        for (int j = 0; j < 4; ++j)
#pragma unroll
            for (int k = 0; k < 4; ++k) o[i][j][k] = 0.f;

#pragma unroll
    for (int kt = 0; kt < 4; ++kt) {
        uint32_t pa[2][4];
#pragma unroll
        for (int mf = 0; mf < 2; ++mf) {
            pa[mf][0] = h2pack(s[mf][2 * kt][0],     s[mf][2 * kt][1]);
            pa[mf][1] = h2pack(s[mf][2 * kt][2],     s[mf][2 * kt][3]);
            pa[mf][2] = h2pack(s[mf][2 * kt + 1][0], s[mf][2 * kt + 1][1]);
            pa[mf][3] = h2pack(s[mf][2 * kt + 1][2], s[mf][2 * kt + 1][3]);
        }
        uint32_t bv[4][2];
#pragma unroll
        for (int np = 0; np < 2; ++np) {
            uint32_t r4[4];
            uint32_t addr = vtb
                + ((np * 16 + (sel >> 1) * 8 + l8) * VSTR) * 2
                + kt * 32 + (sel & 1) * 16;
            ldsm_x4(r4, addr);
            bv[np * 2 + 0][0] = r4[0]; bv[np * 2 + 0][1] = r4[1];
            bv[np * 2 + 1][0] = r4[2]; bv[np * 2 + 1][1] = r4[3];
        }
#pragma unroll
        for (int mf = 0; mf < 2; ++mf)
#pragma unroll
            for (int nf = 0; nf < 4; ++nf)
                mma16816(o[mf][nf], pa[mf], bv[nf]);
    }

    // ---- normalize + store fp16 to gOh ----
#pragma unroll
    for (int mf = 0; mf < 2; ++mf) {
        int rA = wi * 32 + mf * 16 + g;
        int rB = rA + 8;
#pragma unroll
        for (int nf = 0; nf < 4; ++nf) {
            int d = nf * 8 + cq * 2;
            if (rA < NTOK) {
                *(uint32_t*)(gOh + (size_t)(w * NTOK + rA) * CDIM + h * HD + d) =
                    h2pack(o[mf][nf][0] * inv[mf][0], o[mf][nf][1] * inv[mf][0]);
            }
            if (rB < NTOK) {
                *(uint32_t*)(gOh + (size_t)(w * NTOK + rB) * CDIM + h * HD + d) =
                    h2pack(o[mf][nf][2] * inv[mf][1], o[mf][nf][3] * inv[mf][1]);
            }
        }
    }
}

// ---------------- launch ----------------
extern "C" void kernel_launch(void* const* d_in, const int* in_sizes, int n_in,
                              void* d_out, int out_size) {
    (void)in_sizes; (void)n_in; (void)out_size;
    const float* x      = (const float*)d_in[0];
    const float* qkv_w  = (const float*)d_in[1];
    const float* qkv_b  = (const float*)d_in[2];
    const float* proj_w = (const float*)d_in[3];
    const float* proj_b = (const float*)d_in[4];
    const float* rpt    = (const float*)d_in[5];
    float* out = (float*)d_out;

    cudaFuncSetAttribute(mma_gemm, cudaFuncAttributeMaxDynamicSharedMemorySize, SMEM_SZ);

    __half *pXh, *pOh, *pWh, *pPh;
    cudaGetSymbolAddress((void**)&pXh, gXh);
    cudaGetSymbolAddress((void**)&pOh, gOh);
    cudaGetSymbolAddress((void**)&pWh, gWh);
    cudaGetSymbolAddress((void**)&pPh, gPh);

    bias_kernel<<<(NHEAD * NTOK * NTOK + 255) / 256, 256>>>(rpt);
    gather_h<<<(MROWS * (CDIM / 4) + 255) / 256, 256>>>(x);
    wsplit_h<<<(QKVN * CDIM + 255) / 256, 256>>>(qkv_w, pWh, QKVN, CDIM);
    wsplit_h<<<(CDIM * CDIM + 255) / 256, 256>>>(proj_w, pPh, CDIM, CDIM);

    dim3 g1(QKVN / TN, MROWS / TM);   // (9, 784)
    mma_gemm<<<g1, 256, SMEM_SZ>>>(pXh, pWh, qkv_b, nullptr, 0);

    attn_mma<<<BW * NHEAD, 64>>>();

    dim3 g2(CDIM / TN, MROWS / TM);   // (3, 784)
    mma_gemm<<<g2, 256, SMEM_SZ>>>(pOh, pPh, proj_b, out, 1);
}